// round 3
// baseline (speedup 1.0000x reference)
#include <cuda_runtime.h>

// Problem constants (fixed by the dataset)
#define MAXN 50000
#define MAXE 800000

// Persistent device scratch (allocation-free rule: __device__ globals)
static __device__ __align__(16) float g_sup[MAXN * 32];     // s_up   [n][c]
static __device__ __align__(16) float g_vup[MAXN * 96];     // v_up   [n][x][c]
static __device__ __align__(16) float g_skip_s[MAXN * 64];  // skip_s [n][d]
static __device__ __align__(16) float g_skip_v[MAXN * 96];  // skip_v [n][x][c]

// CSR-by-receiver scratch + permuted edge payload (SoA)
static __device__ int g_cnt[MAXN];
static __device__ int g_off[MAXN + 1];
static __device__ int g_cur[MAXN];
static __device__ int g_bsum[64];
static __device__ int g_psnd[MAXE];
static __device__ __align__(16) float4 g_psh[MAXE];      // edge_features, permuted
static __device__ __align__(16) float4 g_prad[MAXE * 2]; // radial (8 floats), permuted

__device__ __forceinline__ float silu_f(float x) {
    return x / (1.0f + __expf(-x));
}

// ---------------------------------------------------------------------------
// Kernel A: per-node up-projection + species skip. Warp per node; lane = chan.
// Also zeroes the receiver histogram.
// ---------------------------------------------------------------------------
__global__ void node_up_kernel(const float* __restrict__ nf,
                               const int*   __restrict__ species,
                               const float* __restrict__ Wus,   // (32,32)
                               const float* __restrict__ Wuv,   // (32,32)
                               const float* __restrict__ Wss,   // (5,32,64)
                               const float* __restrict__ Wsv,   // (5,32,32)
                               int N)
{
    int warp = (blockIdx.x * blockDim.x + threadIdx.x) >> 5;
    int lane = threadIdx.x & 31;
    if (warp >= N) return;
    int n = warp;

    if (lane == 0) g_cnt[n] = 0;

    const float* nfp = nf + (size_t)n * 128;
    float s  = nfp[lane];
    float v0 = nfp[32 + lane * 3 + 0];
    float v1 = nfp[32 + lane * 3 + 1];
    float v2 = nfp[32 + lane * 3 + 2];
    int sp = species[n];
    const float* wss = Wss + sp * 2048;
    const float* wsv = Wsv + sp * 1024;

    float sup = 0.f, vu0 = 0.f, vu1 = 0.f, vu2 = 0.f;
    float ss0 = 0.f, ss1 = 0.f, sv0 = 0.f, sv1 = 0.f, sv2 = 0.f;

    #pragma unroll
    for (int c = 0; c < 32; ++c) {
        float sb = __shfl_sync(0xffffffffu, s,  c);
        float b0 = __shfl_sync(0xffffffffu, v0, c);
        float b1 = __shfl_sync(0xffffffffu, v1, c);
        float b2 = __shfl_sync(0xffffffffu, v2, c);
        sup = fmaf(sb, __ldg(Wus + c * 32 + lane), sup);
        float wu = __ldg(Wuv + c * 32 + lane);
        vu0 = fmaf(b0, wu, vu0);
        vu1 = fmaf(b1, wu, vu1);
        vu2 = fmaf(b2, wu, vu2);
        ss0 = fmaf(sb, __ldg(wss + c * 64 + lane), ss0);
        ss1 = fmaf(sb, __ldg(wss + c * 64 + 32 + lane), ss1);
        float wv = __ldg(wsv + c * 32 + lane);
        sv0 = fmaf(b0, wv, sv0);
        sv1 = fmaf(b1, wv, sv1);
        sv2 = fmaf(b2, wv, sv2);
    }

    const float isc = 0.17677669529663687f; // 1/sqrt(32)
    g_sup[n * 32 + lane]             = sup * isc;
    g_vup[n * 96 + 0 * 32 + lane]    = vu0 * isc;
    g_vup[n * 96 + 1 * 32 + lane]    = vu1 * isc;
    g_vup[n * 96 + 2 * 32 + lane]    = vu2 * isc;
    g_skip_s[n * 64 + lane]          = ss0 * isc;
    g_skip_s[n * 64 + 32 + lane]     = ss1 * isc;
    g_skip_v[n * 96 + 0 * 32 + lane] = sv0 * isc;
    g_skip_v[n * 96 + 1 * 32 + lane] = sv1 * isc;
    g_skip_v[n * 96 + 2 * 32 + lane] = sv2 * isc;
}

// ---------------------------------------------------------------------------
// Counting sort by receiver: histogram -> scan (3 phases) -> payload permute
// ---------------------------------------------------------------------------
__global__ void hist_kernel(const int* __restrict__ rcv, int E)
{
    int e = blockIdx.x * blockDim.x + threadIdx.x;
    if (e < E) atomicAdd(&g_cnt[__ldg(rcv + e)], 1);
}

__global__ void scan1_kernel(int N)
{
    __shared__ int wsum[32];
    int t = threadIdx.x, b = blockIdx.x;
    int idx = b * 1024 + t;
    int val = (idx < N) ? g_cnt[idx] : 0;
    int lane = t & 31, wid = t >> 5;
    int x = val;
    #pragma unroll
    for (int o = 1; o < 32; o <<= 1) {
        int y = __shfl_up_sync(0xffffffffu, x, o);
        if (lane >= o) x += y;
    }
    if (lane == 31) wsum[wid] = x;
    __syncthreads();
    if (wid == 0) {
        int w = wsum[lane];
        #pragma unroll
        for (int o = 1; o < 32; o <<= 1) {
            int y = __shfl_up_sync(0xffffffffu, w, o);
            if (lane >= o) w += y;
        }
        wsum[lane] = w;
    }
    __syncthreads();
    int basev = wid ? wsum[wid - 1] : 0;
    int incl = x + basev;
    if (idx < N) g_off[idx] = incl - val;   // block-local exclusive
    if (t == 1023) g_bsum[b] = incl;        // block total
}

__global__ void scan2_kernel(int nb, int N)
{
    if (threadIdx.x == 0 && blockIdx.x == 0) {
        int run = 0;
        for (int b = 0; b < nb; ++b) { int v = g_bsum[b]; g_bsum[b] = run; run += v; }
        g_off[N] = run;
    }
}

__global__ void scan3_kernel(int N)
{
    int idx = blockIdx.x * 1024 + threadIdx.x;
    if (idx < N) {
        int o = g_off[idx] + g_bsum[blockIdx.x];
        g_off[idx] = o;
        g_cur[idx] = o;
    }
}

// Permute full edge payload into receiver-sorted SoA arrays.
__global__ void reorder_kernel(const int* __restrict__ rcv,
                               const int* __restrict__ snd,
                               const float* __restrict__ ef,
                               const float* __restrict__ radial,
                               int E)
{
    int e = blockIdx.x * blockDim.x + threadIdx.x;
    if (e >= E) return;
    int pos = atomicAdd(&g_cur[__ldg(rcv + e)], 1);
    g_psnd[pos] = __ldg(snd + e);
    g_psh[pos]  = __ldg((const float4*)(ef + (size_t)e * 4));
    g_prad[pos * 2 + 0] = __ldg((const float4*)(radial + (size_t)e * 8));
    g_prad[pos * 2 + 1] = __ldg((const float4*)(radial + (size_t)e * 8 + 4));
}

// ---------------------------------------------------------------------------
// Kernel B: fused node-centric aggregation + down-projection + gated output.
// Warp per receiver node. Wr1/Wr2 slices register-resident. Register
// accumulation (no atomics); smem transpose tile bridges agg -> down layouts.
// Lane layout (verified in rounds 1-2):
//   producer lane P computes w[path=P>>3][4*(P&7)..+3]
//   consumer lane L owns quad qA = slot(L>>4), chans 4*(L&15);  qB = slot+2
// ---------------------------------------------------------------------------
__global__ void __launch_bounds__(256) agg_down_kernel(
    const float* __restrict__ Wr1,   // (8,8)
    const float* __restrict__ Wr2,   // (8,128)
    const float* __restrict__ Wds,   // (64,64)
    const float* __restrict__ Wdv,   // (64,32)
    float* __restrict__ out,
    int N)
{
    __shared__ float smtile[8][256];

    int warp = (blockIdx.x * blockDim.x + threadIdx.x) >> 5;
    int lane = threadIdx.x & 31;
    int wib  = (threadIdx.x >> 5);
    if (warp >= N) return;
    int n = warp;

    const float inv_sqrt8 = 0.35355339059327373f;
    const float inv_sqrt3 = 0.5773502691896258f;

    int grp  = lane >> 3;
    int srcA = (grp == 0) ? lane : ((grp == 1) ? lane + 16 : lane - 8);
    int srcB = (grp < 2)  ? lane + 8 : srcA;
    int cidx = (lane & 7) * 4;
    int jj   = lane & 7;

    // Hoist radial-MLP weights into registers (loop-invariant per lane)
    float wr1r[8];
    #pragma unroll
    for (int i = 0; i < 8; ++i) wr1r[i] = __ldg(Wr1 + i * 8 + jj);
    float4 wr2r[8];
    #pragma unroll
    for (int q = 0; q < 8; ++q) wr2r[q] = __ldg((const float4*)(Wr2 + q * 128 + lane * 4));

    int beg = g_off[n], end = g_off[n + 1];

    float aA0 = 0.f, aA1 = 0.f, aA2 = 0.f, aA3 = 0.f;
    float aB0 = 0.f, aB1 = 0.f, aB2 = 0.f, aB3 = 0.f;

    for (int base = beg; base < end; base += 32) {
        int sndl = 0;
        if (base + lane < end) sndl = __ldg(g_psnd + base + lane);
        int m = end - base; if (m > 32) m = 32;

        for (int j = 0; j < m; ++j) {
            int snd = __shfl_sync(0xffffffffu, sndl, j);
            int pos = base + j;

            // radial MLP hidden layer (broadcast loads, sequential -> L1 hits)
            float4 r0 = __ldg(g_prad + pos * 2 + 0);
            float4 r1 = __ldg(g_prad + pos * 2 + 1);
            float h;
            {
                float t = r0.x * wr1r[0];
                t = fmaf(r0.y, wr1r[1], t);
                t = fmaf(r0.z, wr1r[2], t);
                t = fmaf(r0.w, wr1r[3], t);
                t = fmaf(r1.x, wr1r[4], t);
                t = fmaf(r1.y, wr1r[5], t);
                t = fmaf(r1.z, wr1r[6], t);
                t = fmaf(r1.w, wr1r[7], t);
                h = silu_f(t * inv_sqrt8);
            }

            // producer w from register-resident Wr2
            float w0 = 0.f, w1 = 0.f, w2 = 0.f, w3 = 0.f;
            #pragma unroll
            for (int q = 0; q < 8; ++q) {
                float hq = __shfl_sync(0xffffffffu, h, q);
                w0 = fmaf(hq, wr2r[q].x, w0);
                w1 = fmaf(hq, wr2r[q].y, w1);
                w2 = fmaf(hq, wr2r[q].z, w2);
                w3 = fmaf(hq, wr2r[q].w, w3);
            }
            w0 *= inv_sqrt8; w1 *= inv_sqrt8; w2 *= inv_sqrt8; w3 *= inv_sqrt8;

            float wA0 = __shfl_sync(0xffffffffu, w0, srcA);
            float wA1 = __shfl_sync(0xffffffffu, w1, srcA);
            float wA2 = __shfl_sync(0xffffffffu, w2, srcA);
            float wA3 = __shfl_sync(0xffffffffu, w3, srcA);
            float wB0 = __shfl_sync(0xffffffffu, w0, srcB);
            float wB1 = __shfl_sync(0xffffffffu, w1, srcB);
            float wB2 = __shfl_sync(0xffffffffu, w2, srcB);
            float wB3 = __shfl_sync(0xffffffffu, w3, srcB);

            float4 sh = __ldg(g_psh + pos);

            float vA0, vA1, vA2, vA3, vB0, vB1, vB2, vB3;

            if ((grp & 1) == 0) {
                float4 se = __ldg((const float4*)(g_sup + (size_t)snd * 32 + cidx));
                if (grp == 0) {
                    vA0 = wA0 * se.x * sh.x; vA1 = wA1 * se.y * sh.x;
                    vA2 = wA2 * se.z * sh.x; vA3 = wA3 * se.w * sh.x;
                    vB0 = wB0 * se.x * sh.z; vB1 = wB1 * se.y * sh.z;
                    vB2 = wB2 * se.z * sh.z; vB3 = wB3 * se.w * sh.z;
                } else {
                    vA0 = wA0 * se.x * sh.y; vA1 = wA1 * se.y * sh.y;
                    vA2 = wA2 * se.z * sh.y; vA3 = wA3 * se.w * sh.y;
                    vB0 = wA0 * se.x * sh.w; vB1 = wA1 * se.y * sh.w;
                    vB2 = wA2 * se.z * sh.w; vB3 = wA3 * se.w * sh.w;
                }
            } else {
                const float* vb = g_vup + (size_t)snd * 96 + cidx;
                if (grp == 1) {
                    float4 ve0 = __ldg((const float4*)(vb));
                    float4 ve1 = __ldg((const float4*)(vb + 32));
                    float4 ve2 = __ldg((const float4*)(vb + 64));
                    float d0 = ve0.x * sh.y + ve1.x * sh.z + ve2.x * sh.w;
                    float d1 = ve0.y * sh.y + ve1.y * sh.z + ve2.y * sh.w;
                    float d2 = ve0.z * sh.y + ve1.z * sh.z + ve2.z * sh.w;
                    float d3 = ve0.w * sh.y + ve1.w * sh.z + ve2.w * sh.w;
                    vA0 = wA0 * d0 * inv_sqrt3; vA1 = wA1 * d1 * inv_sqrt3;
                    vA2 = wA2 * d2 * inv_sqrt3; vA3 = wA3 * d3 * inv_sqrt3;
                    vB0 = wB0 * ve1.x * sh.x; vB1 = wB1 * ve1.y * sh.x;
                    vB2 = wB2 * ve1.z * sh.x; vB3 = wB3 * ve1.w * sh.x;
                } else {
                    float4 ve0 = __ldg((const float4*)(vb));
                    float4 ve2 = __ldg((const float4*)(vb + 64));
                    vA0 = wA0 * ve0.x * sh.x; vA1 = wA1 * ve0.y * sh.x;
                    vA2 = wA2 * ve0.z * sh.x; vA3 = wA3 * ve0.w * sh.x;
                    vB0 = wA0 * ve2.x * sh.x; vB1 = wA1 * ve2.y * sh.x;
                    vB2 = wA2 * ve2.z * sh.x; vB3 = wA3 * ve2.w * sh.x;
                }
            }

            aA0 += vA0; aA1 += vA1; aA2 += vA2; aA3 += vA3;
            aB0 += vB0; aB1 += vB1; aB2 += vB2; aB3 += vB3;
        }
    }

    // ---- transpose agg quads into node_down lane layout via smem tile ----
    const float qdeg = 0.25f; // 1/sqrt(16)
    {
        float* dst = &smtile[wib][(lane >> 4) * 64 + (lane & 15) * 4];
        dst[0]   = aA0 * qdeg; dst[1]   = aA1 * qdeg;
        dst[2]   = aA2 * qdeg; dst[3]   = aA3 * qdeg;
        dst[128] = aB0 * qdeg; dst[129] = aB1 * qdeg;
        dst[130] = aB2 * qdeg; dst[131] = aB3 * qdeg;
    }
    __syncwarp();

    const float* ag = smtile[wib];
    float a0l  = ag[lane],        a0h  = ag[32 + lane];
    float a1l0 = ag[64 + lane],   a1h0 = ag[96 + lane];
    float a1l1 = ag[128 + lane],  a1h1 = ag[160 + lane];
    float a1l2 = ag[192 + lane],  a1h2 = ag[224 + lane];

    float sc0 = 0.f, sc1 = 0.f, vc0 = 0.f, vc1 = 0.f, vc2 = 0.f;

    #pragma unroll
    for (int c = 0; c < 32; ++c) {
        float b0 = __shfl_sync(0xffffffffu, a0l, c);
        float b1 = __shfl_sync(0xffffffffu, a0h, c);
        sc0 = fmaf(b0, __ldg(Wds + c * 64 + lane), sc0);
        sc0 = fmaf(b1, __ldg(Wds + (32 + c) * 64 + lane), sc0);
        sc1 = fmaf(b0, __ldg(Wds + c * 64 + 32 + lane), sc1);
        sc1 = fmaf(b1, __ldg(Wds + (32 + c) * 64 + 32 + lane), sc1);
        float wv0 = __ldg(Wdv + c * 32 + lane);
        float wv1 = __ldg(Wdv + (32 + c) * 32 + lane);
        vc0 = fmaf(__shfl_sync(0xffffffffu, a1l0, c), wv0, vc0);
        vc0 = fmaf(__shfl_sync(0xffffffffu, a1h0, c), wv1, vc0);
        vc1 = fmaf(__shfl_sync(0xffffffffu, a1l1, c), wv0, vc1);
        vc1 = fmaf(__shfl_sync(0xffffffffu, a1h1, c), wv1, vc1);
        vc2 = fmaf(__shfl_sync(0xffffffffu, a1l2, c), wv0, vc2);
        vc2 = fmaf(__shfl_sync(0xffffffffu, a1h2, c), wv1, vc2);
    }

    const float i2c = 0.125f; // 1/sqrt(64)
    float scl = 0.5f * (sc0 * i2c + g_skip_s[n * 64 + lane]);
    float sch = 0.5f * (sc1 * i2c + g_skip_s[n * 64 + 32 + lane]);
    float feat = silu_f(scl);
    float gate = silu_f(sch);

    float vg0 = 0.5f * (vc0 * i2c + g_skip_v[n * 96 +      lane]) * gate;
    float vg1 = 0.5f * (vc1 * i2c + g_skip_v[n * 96 + 32 + lane]) * gate;
    float vg2 = 0.5f * (vc2 * i2c + g_skip_v[n * 96 + 64 + lane]) * gate;

    float* o = out + (size_t)n * 128;
    o[lane] = feat;
    o[32 + 3 * lane + 0] = vg0;
    o[32 + 3 * lane + 1] = vg1;
    o[32 + 3 * lane + 2] = vg2;
}

// ---------------------------------------------------------------------------
extern "C" void kernel_launch(void* const* d_in, const int* in_sizes, int n_in,
                              void* d_out, int out_size)
{
    const float* nf      = (const float*)d_in[0];
    const float* ef      = (const float*)d_in[1];
    const float* radial  = (const float*)d_in[2];
    const int*   snd     = (const int*)  d_in[3];
    const int*   rcv     = (const int*)  d_in[4];
    const int*   species = (const int*)  d_in[5];
    const float* Wus     = (const float*)d_in[6];
    const float* Wuv     = (const float*)d_in[7];
    const float* Wr1     = (const float*)d_in[8];
    const float* Wr2     = (const float*)d_in[9];
    const float* Wds     = (const float*)d_in[10];
    const float* Wdv     = (const float*)d_in[11];
    const float* Wss     = (const float*)d_in[12];
    const float* Wsv     = (const float*)d_in[13];
    float* out = (float*)d_out;

    int N = in_sizes[0] / 128;
    int E = in_sizes[3];
    int nb = (N + 1023) / 1024;

    // node_up also zeroes g_cnt (must precede hist)
    node_up_kernel <<<(N + 7) / 8, 256>>>(nf, species, Wus, Wuv, Wss, Wsv, N);
    hist_kernel    <<<(E + 255) / 256, 256>>>(rcv, E);
    scan1_kernel   <<<nb, 1024>>>(N);
    scan2_kernel   <<<1, 32>>>(nb, N);
    scan3_kernel   <<<nb, 1024>>>(N);
    reorder_kernel <<<(E + 255) / 256, 256>>>(rcv, snd, ef, radial, E);
    agg_down_kernel<<<(N + 7) / 8, 256>>>(Wr1, Wr2, Wds, Wdv, out, N);
}

// round 4
// speedup vs baseline: 1.4957x; 1.4957x over previous
#include <cuda_runtime.h>

// Problem constants (fixed by the dataset)
#define MAXN 50000
#define MAXE 800000

// Persistent device scratch (allocation-free rule: __device__ globals)
static __device__ __align__(16) float g_sup[MAXN * 32];     // s_up   [n][c]
static __device__ __align__(16) float g_vup[MAXN * 96];     // v_up   [n][x][c]
static __device__ __align__(16) float g_skip_s[MAXN * 64];  // skip_s [n][d]
static __device__ __align__(16) float g_skip_v[MAXN * 96];  // skip_v [n][x][c]
static __device__ __align__(16) float g_agg[MAXN * 256];    // [n][slot][c]

__device__ __forceinline__ float silu_f(float x) {
    return x / (1.0f + __expf(-x));
}

__device__ __forceinline__ void red_add_v4(float* p, float a, float b, float c, float d) {
    asm volatile("red.global.add.v4.f32 [%0], {%1,%2,%3,%4};"
                 :: "l"(p), "f"(a), "f"(b), "f"(c), "f"(d)
                 : "memory");
}

// ---------------------------------------------------------------------------
// Kernel A: per-node up-projection + species skip (UNCHANGED from round 1).
// Warp per node; lane = channel. Also zeroes this node's agg slab.
// ---------------------------------------------------------------------------
__global__ void node_up_kernel(const float* __restrict__ nf,
                               const int*   __restrict__ species,
                               const float* __restrict__ Wus,   // (32,32)
                               const float* __restrict__ Wuv,   // (32,32)
                               const float* __restrict__ Wss,   // (5,32,64)
                               const float* __restrict__ Wsv,   // (5,32,32)
                               int N)
{
    int warp = (blockIdx.x * blockDim.x + threadIdx.x) >> 5;
    int lane = threadIdx.x & 31;
    if (warp >= N) return;
    int n = warp;

    const float* nfp = nf + (size_t)n * 128;
    float s  = nfp[lane];
    float v0 = nfp[32 + lane * 3 + 0];
    float v1 = nfp[32 + lane * 3 + 1];
    float v2 = nfp[32 + lane * 3 + 2];
    int sp = species[n];
    const float* wss = Wss + sp * 2048;
    const float* wsv = Wsv + sp * 1024;

    float sup = 0.f, vu0 = 0.f, vu1 = 0.f, vu2 = 0.f;
    float ss0 = 0.f, ss1 = 0.f, sv0 = 0.f, sv1 = 0.f, sv2 = 0.f;

    #pragma unroll
    for (int c = 0; c < 32; ++c) {
        float sb = __shfl_sync(0xffffffffu, s,  c);
        float b0 = __shfl_sync(0xffffffffu, v0, c);
        float b1 = __shfl_sync(0xffffffffu, v1, c);
        float b2 = __shfl_sync(0xffffffffu, v2, c);
        sup = fmaf(sb, __ldg(Wus + c * 32 + lane), sup);
        float wu = __ldg(Wuv + c * 32 + lane);
        vu0 = fmaf(b0, wu, vu0);
        vu1 = fmaf(b1, wu, vu1);
        vu2 = fmaf(b2, wu, vu2);
        ss0 = fmaf(sb, __ldg(wss + c * 64 + lane), ss0);
        ss1 = fmaf(sb, __ldg(wss + c * 64 + 32 + lane), ss1);
        float wv = __ldg(wsv + c * 32 + lane);
        sv0 = fmaf(b0, wv, sv0);
        sv1 = fmaf(b1, wv, sv1);
        sv2 = fmaf(b2, wv, sv2);
    }

    const float isc = 0.17677669529663687f; // 1/sqrt(32)
    g_sup[n * 32 + lane]             = sup * isc;
    g_vup[n * 96 + 0 * 32 + lane]    = vu0 * isc;
    g_vup[n * 96 + 1 * 32 + lane]    = vu1 * isc;
    g_vup[n * 96 + 2 * 32 + lane]    = vu2 * isc;
    g_skip_s[n * 64 + lane]          = ss0 * isc;
    g_skip_s[n * 64 + 32 + lane]     = ss1 * isc;
    g_skip_v[n * 96 + 0 * 32 + lane] = sv0 * isc;
    g_skip_v[n * 96 + 1 * 32 + lane] = sv1 * isc;
    g_skip_v[n * 96 + 2 * 32 + lane] = sv2 * isc;

    // Zero this node's accumulator slab (must precede edge kernel).
    #pragma unroll
    for (int k = 0; k < 2; ++k)
        *(float4*)(g_agg + n * 256 + (k * 32 + lane) * 4) = make_float4(0.f, 0.f, 0.f, 0.f);
}

// ---------------------------------------------------------------------------
// Kernel B: edge kernel, 8 edges per warp. Wr1/Wr2 register-resident
// (amortized 8x); radial/indices batch-loaded coalesced; fixed trip count
// lets ptxas unroll & pipeline the gathers. Lane math identical to round 1:
//   producer lane P computes w[path=P>>3][4*(P&7)..+3]
//   consumer lane L owns quad qA = slot(L>>4), chans 4*(L&15);  qB = slot+2
// ---------------------------------------------------------------------------
__global__ void __launch_bounds__(256) edge_kernel(
    const float* __restrict__ ef,
    const float* __restrict__ radial,
    const int*   __restrict__ snd_,
    const int*   __restrict__ rcv_,
    const float* __restrict__ Wr1,   // (8,8)
    const float* __restrict__ Wr2,   // (8,128)
    int E)
{
    int warp = (blockIdx.x * blockDim.x + threadIdx.x) >> 5;
    int lane = threadIdx.x & 31;
    int base = warp * 8;
    if (base >= E) return;

    const float inv_sqrt8 = 0.35355339059327373f;
    const float inv_sqrt3 = 0.5773502691896258f;
    const float qdeg      = 0.25f; // 1/sqrt(16)

    int grp  = lane >> 3;
    int srcA = (grp == 0) ? lane : ((grp == 1) ? lane + 16 : lane - 8);
    int srcB = (grp < 2)  ? lane + 8 : srcA;
    int cidx = (lane & 7) * 4;
    int jj   = lane & 7;

    // Per-warp invariant weights (amortized over 8 edges)
    float wr1r[8];
    #pragma unroll
    for (int i = 0; i < 8; ++i) wr1r[i] = __ldg(Wr1 + i * 8 + jj);
    float4 wr2r[8];
    #pragma unroll
    for (int q = 0; q < 8; ++q) wr2r[q] = __ldg((const float4*)(Wr2 + q * 128 + lane * 4));

    // Batch-load 8 edges' indices (lanes 0-7 hold edges 0-7; repeated x4)
    int ei = base + jj;
    bool vld = (ei < E);
    int snd8 = vld ? __ldg(snd_ + ei) : 0;
    int rcv8 = vld ? __ldg(rcv_ + ei) : 0;

    // Batch-load 8 edges' radial (64 floats, coalesced): lane holds float2
    // covering floats [base*8 + 2*lane, +1]; edge j's r_i lives at lane
    // 4*j + (i>>1), component i&1.
    float rvx = 0.f, rvy = 0.f;
    if (base + (lane >> 2) < E) {
        float2 rv = __ldg((const float2*)radial + (size_t)base * 4 + lane);
        rvx = rv.x; rvy = rv.y;
    }

    int m = E - base; if (m > 8) m = 8;

    #pragma unroll
    for (int j = 0; j < 8; ++j) {
        if (j >= m) break;
        int snd = __shfl_sync(0xffffffffu, snd8, j);
        int rcv = __shfl_sync(0xffffffffu, rcv8, j);

        // radial hidden layer: h_{jj} via shuffles of batched radial
        float a0x = __shfl_sync(0xffffffffu, rvx, 4 * j + 0);
        float a0y = __shfl_sync(0xffffffffu, rvy, 4 * j + 0);
        float a1x = __shfl_sync(0xffffffffu, rvx, 4 * j + 1);
        float a1y = __shfl_sync(0xffffffffu, rvy, 4 * j + 1);
        float a2x = __shfl_sync(0xffffffffu, rvx, 4 * j + 2);
        float a2y = __shfl_sync(0xffffffffu, rvy, 4 * j + 2);
        float a3x = __shfl_sync(0xffffffffu, rvx, 4 * j + 3);
        float a3y = __shfl_sync(0xffffffffu, rvy, 4 * j + 3);
        float t = a0x * wr1r[0];
        t = fmaf(a0y, wr1r[1], t);
        t = fmaf(a1x, wr1r[2], t);
        t = fmaf(a1y, wr1r[3], t);
        t = fmaf(a2x, wr1r[4], t);
        t = fmaf(a2y, wr1r[5], t);
        t = fmaf(a3x, wr1r[6], t);
        t = fmaf(a3y, wr1r[7], t);
        float h = silu_f(t * inv_sqrt8);

        // producer w from register-resident Wr2
        float w0 = 0.f, w1 = 0.f, w2 = 0.f, w3 = 0.f;
        #pragma unroll
        for (int q = 0; q < 8; ++q) {
            float hq = __shfl_sync(0xffffffffu, h, q);
            w0 = fmaf(hq, wr2r[q].x, w0);
            w1 = fmaf(hq, wr2r[q].y, w1);
            w2 = fmaf(hq, wr2r[q].z, w2);
            w3 = fmaf(hq, wr2r[q].w, w3);
        }
        w0 *= inv_sqrt8; w1 *= inv_sqrt8; w2 *= inv_sqrt8; w3 *= inv_sqrt8;

        float wA0 = __shfl_sync(0xffffffffu, w0, srcA);
        float wA1 = __shfl_sync(0xffffffffu, w1, srcA);
        float wA2 = __shfl_sync(0xffffffffu, w2, srcA);
        float wA3 = __shfl_sync(0xffffffffu, w3, srcA);
        float wB0 = __shfl_sync(0xffffffffu, w0, srcB);
        float wB1 = __shfl_sync(0xffffffffu, w1, srcB);
        float wB2 = __shfl_sync(0xffffffffu, w2, srcB);
        float wB3 = __shfl_sync(0xffffffffu, w3, srcB);

        float4 sh = __ldg((const float4*)ef + (base + j));   // broadcast

        float vA0, vA1, vA2, vA3, vB0, vB1, vB2, vB3;

        if ((grp & 1) == 0) {
            float4 se = __ldg((const float4*)(g_sup + (size_t)snd * 32 + cidx));
            if (grp == 0) {
                vA0 = wA0 * se.x * sh.x; vA1 = wA1 * se.y * sh.x;
                vA2 = wA2 * se.z * sh.x; vA3 = wA3 * se.w * sh.x;
                vB0 = wB0 * se.x * sh.z; vB1 = wB1 * se.y * sh.z;
                vB2 = wB2 * se.z * sh.z; vB3 = wB3 * se.w * sh.z;
            } else {
                vA0 = wA0 * se.x * sh.y; vA1 = wA1 * se.y * sh.y;
                vA2 = wA2 * se.z * sh.y; vA3 = wA3 * se.w * sh.y;
                vB0 = wA0 * se.x * sh.w; vB1 = wA1 * se.y * sh.w;
                vB2 = wA2 * se.z * sh.w; vB3 = wA3 * se.w * sh.w;
            }
        } else {
            const float* vb = g_vup + (size_t)snd * 96 + cidx;
            if (grp == 1) {
                float4 ve0 = __ldg((const float4*)(vb));
                float4 ve1 = __ldg((const float4*)(vb + 32));
                float4 ve2 = __ldg((const float4*)(vb + 64));
                float d0 = ve0.x * sh.y + ve1.x * sh.z + ve2.x * sh.w;
                float d1 = ve0.y * sh.y + ve1.y * sh.z + ve2.y * sh.w;
                float d2 = ve0.z * sh.y + ve1.z * sh.z + ve2.z * sh.w;
                float d3 = ve0.w * sh.y + ve1.w * sh.z + ve2.w * sh.w;
                vA0 = wA0 * d0 * inv_sqrt3; vA1 = wA1 * d1 * inv_sqrt3;
                vA2 = wA2 * d2 * inv_sqrt3; vA3 = wA3 * d3 * inv_sqrt3;
                vB0 = wB0 * ve1.x * sh.x; vB1 = wB1 * ve1.y * sh.x;
                vB2 = wB2 * ve1.z * sh.x; vB3 = wB3 * ve1.w * sh.x;
            } else {
                float4 ve0 = __ldg((const float4*)(vb));
                float4 ve2 = __ldg((const float4*)(vb + 64));
                vA0 = wA0 * ve0.x * sh.x; vA1 = wA1 * ve0.y * sh.x;
                vA2 = wA2 * ve0.z * sh.x; vA3 = wA3 * ve0.w * sh.x;
                vB0 = wA0 * ve2.x * sh.x; vB1 = wA1 * ve2.y * sh.x;
                vB2 = wA2 * ve2.z * sh.x; vB3 = wA3 * ve2.w * sh.x;
            }
        }

        float* dst = g_agg + (size_t)rcv * 256 + (lane >> 4) * 64 + (lane & 15) * 4;
        red_add_v4(dst,       vA0 * qdeg, vA1 * qdeg, vA2 * qdeg, vA3 * qdeg);
        red_add_v4(dst + 128, vB0 * qdeg, vB1 * qdeg, vB2 * qdeg, vB3 * qdeg);
    }
}

// ---------------------------------------------------------------------------
// Kernel C: per-node down-projection + skip average + gated output
// (UNCHANGED from round 1).
// ---------------------------------------------------------------------------
__global__ void node_down_kernel(const float* __restrict__ Wds,  // (64,64)
                                 const float* __restrict__ Wdv,  // (64,32)
                                 float* __restrict__ out,
                                 int N)
{
    int warp = (blockIdx.x * blockDim.x + threadIdx.x) >> 5;
    int lane = threadIdx.x & 31;
    if (warp >= N) return;
    int n = warp;

    const float* ag = g_agg + (size_t)n * 256;
    float a0l  = ag[lane],        a0h  = ag[32 + lane];
    float a1l0 = ag[64 + lane],   a1h0 = ag[96 + lane];
    float a1l1 = ag[128 + lane],  a1h1 = ag[160 + lane];
    float a1l2 = ag[192 + lane],  a1h2 = ag[224 + lane];

    float sc0 = 0.f, sc1 = 0.f, vc0 = 0.f, vc1 = 0.f, vc2 = 0.f;

    #pragma unroll
    for (int c = 0; c < 32; ++c) {
        float b0 = __shfl_sync(0xffffffffu, a0l, c);
        float b1 = __shfl_sync(0xffffffffu, a0h, c);
        sc0 = fmaf(b0, __ldg(Wds + c * 64 + lane), sc0);
        sc0 = fmaf(b1, __ldg(Wds + (32 + c) * 64 + lane), sc0);
        sc1 = fmaf(b0, __ldg(Wds + c * 64 + 32 + lane), sc1);
        sc1 = fmaf(b1, __ldg(Wds + (32 + c) * 64 + 32 + lane), sc1);
        float wv0 = __ldg(Wdv + c * 32 + lane);
        float wv1 = __ldg(Wdv + (32 + c) * 32 + lane);
        vc0 = fmaf(__shfl_sync(0xffffffffu, a1l0, c), wv0, vc0);
        vc0 = fmaf(__shfl_sync(0xffffffffu, a1h0, c), wv1, vc0);
        vc1 = fmaf(__shfl_sync(0xffffffffu, a1l1, c), wv0, vc1);
        vc1 = fmaf(__shfl_sync(0xffffffffu, a1h1, c), wv1, vc1);
        vc2 = fmaf(__shfl_sync(0xffffffffu, a1l2, c), wv0, vc2);
        vc2 = fmaf(__shfl_sync(0xffffffffu, a1h2, c), wv1, vc2);
    }

    const float i2c = 0.125f; // 1/sqrt(64)
    float scl = 0.5f * (sc0 * i2c + g_skip_s[n * 64 + lane]);
    float sch = 0.5f * (sc1 * i2c + g_skip_s[n * 64 + 32 + lane]);
    float feat = silu_f(scl);
    float gate = silu_f(sch);

    float vg0 = 0.5f * (vc0 * i2c + g_skip_v[n * 96 +      lane]) * gate;
    float vg1 = 0.5f * (vc1 * i2c + g_skip_v[n * 96 + 32 + lane]) * gate;
    float vg2 = 0.5f * (vc2 * i2c + g_skip_v[n * 96 + 64 + lane]) * gate;

    float* o = out + (size_t)n * 128;
    o[lane] = feat;
    o[32 + 3 * lane + 0] = vg0;
    o[32 + 3 * lane + 1] = vg1;
    o[32 + 3 * lane + 2] = vg2;
}

// ---------------------------------------------------------------------------
extern "C" void kernel_launch(void* const* d_in, const int* in_sizes, int n_in,
                              void* d_out, int out_size)
{
    const float* nf      = (const float*)d_in[0];
    const float* ef      = (const float*)d_in[1];
    const float* radial  = (const float*)d_in[2];
    const int*   snd     = (const int*)  d_in[3];
    const int*   rcv     = (const int*)  d_in[4];
    const int*   species = (const int*)  d_in[5];
    const float* Wus     = (const float*)d_in[6];
    const float* Wuv     = (const float*)d_in[7];
    const float* Wr1     = (const float*)d_in[8];
    const float* Wr2     = (const float*)d_in[9];
    const float* Wds     = (const float*)d_in[10];
    const float* Wdv     = (const float*)d_in[11];
    const float* Wss     = (const float*)d_in[12];
    const float* Wsv     = (const float*)d_in[13];
    float* out = (float*)d_out;

    int N = in_sizes[0] / 128;
    int E = in_sizes[3];

    int ewarps  = (E + 7) / 8;
    int eblocks = (ewarps + 7) / 8;

    node_up_kernel  <<<(N + 7) / 8, 256>>>(nf, species, Wus, Wuv, Wss, Wsv, N);
    edge_kernel     <<<eblocks, 256>>>(ef, radial, snd, rcv, Wr1, Wr2, E);
    node_down_kernel<<<(N + 7) / 8, 256>>>(Wds, Wdv, out, N);
}

// round 5
// speedup vs baseline: 1.8737x; 1.2528x over previous
#include <cuda_runtime.h>

// Problem constants (fixed by the dataset)
#define MAXN 50000
#define MAXE 800000

// Persistent device scratch (allocation-free rule: __device__ globals)
static __device__ __align__(16) float g_sup[MAXN * 32];     // s_up   [n][c]
static __device__ __align__(16) float g_vup[MAXN * 96];     // v_up   [n][x][c]
static __device__ __align__(16) float g_skip_s[MAXN * 64];  // skip_s [n][d]
static __device__ __align__(16) float g_skip_v[MAXN * 96];  // skip_v [n][x][c]
static __device__ __align__(16) float g_agg[MAXN * 256];    // [n][slot][c]

__device__ __forceinline__ float silu_f(float x) {
    return x / (1.0f + __expf(-x));
}

__device__ __forceinline__ void red_add_v4(float* p, float a, float b, float c, float d) {
    asm volatile("red.global.add.v4.f32 [%0], {%1,%2,%3,%4};"
                 :: "l"(p), "f"(a), "f"(b), "f"(c), "f"(d)
                 : "memory");
}

// ---------------------------------------------------------------------------
// Kernel A: per-node up-projection + species skip (UNCHANGED).
// ---------------------------------------------------------------------------
__global__ void node_up_kernel(const float* __restrict__ nf,
                               const int*   __restrict__ species,
                               const float* __restrict__ Wus,   // (32,32)
                               const float* __restrict__ Wuv,   // (32,32)
                               const float* __restrict__ Wss,   // (5,32,64)
                               const float* __restrict__ Wsv,   // (5,32,32)
                               int N)
{
    int warp = (blockIdx.x * blockDim.x + threadIdx.x) >> 5;
    int lane = threadIdx.x & 31;
    if (warp >= N) return;
    int n = warp;

    const float* nfp = nf + (size_t)n * 128;
    float s  = nfp[lane];
    float v0 = nfp[32 + lane * 3 + 0];
    float v1 = nfp[32 + lane * 3 + 1];
    float v2 = nfp[32 + lane * 3 + 2];
    int sp = species[n];
    const float* wss = Wss + sp * 2048;
    const float* wsv = Wsv + sp * 1024;

    float sup = 0.f, vu0 = 0.f, vu1 = 0.f, vu2 = 0.f;
    float ss0 = 0.f, ss1 = 0.f, sv0 = 0.f, sv1 = 0.f, sv2 = 0.f;

    #pragma unroll
    for (int c = 0; c < 32; ++c) {
        float sb = __shfl_sync(0xffffffffu, s,  c);
        float b0 = __shfl_sync(0xffffffffu, v0, c);
        float b1 = __shfl_sync(0xffffffffu, v1, c);
        float b2 = __shfl_sync(0xffffffffu, v2, c);
        sup = fmaf(sb, __ldg(Wus + c * 32 + lane), sup);
        float wu = __ldg(Wuv + c * 32 + lane);
        vu0 = fmaf(b0, wu, vu0);
        vu1 = fmaf(b1, wu, vu1);
        vu2 = fmaf(b2, wu, vu2);
        ss0 = fmaf(sb, __ldg(wss + c * 64 + lane), ss0);
        ss1 = fmaf(sb, __ldg(wss + c * 64 + 32 + lane), ss1);
        float wv = __ldg(wsv + c * 32 + lane);
        sv0 = fmaf(b0, wv, sv0);
        sv1 = fmaf(b1, wv, sv1);
        sv2 = fmaf(b2, wv, sv2);
    }

    const float isc = 0.17677669529663687f; // 1/sqrt(32)
    g_sup[n * 32 + lane]             = sup * isc;
    g_vup[n * 96 + 0 * 32 + lane]    = vu0 * isc;
    g_vup[n * 96 + 1 * 32 + lane]    = vu1 * isc;
    g_vup[n * 96 + 2 * 32 + lane]    = vu2 * isc;
    g_skip_s[n * 64 + lane]          = ss0 * isc;
    g_skip_s[n * 64 + 32 + lane]     = ss1 * isc;
    g_skip_v[n * 96 + 0 * 32 + lane] = sv0 * isc;
    g_skip_v[n * 96 + 1 * 32 + lane] = sv1 * isc;
    g_skip_v[n * 96 + 2 * 32 + lane] = sv2 * isc;

    #pragma unroll
    for (int k = 0; k < 2; ++k)
        *(float4*)(g_agg + n * 256 + (k * 32 + lane) * 4) = make_float4(0.f, 0.f, 0.f, 0.f);
}

// ---------------------------------------------------------------------------
// Kernel B: edge kernel, 8 edges per warp, BRANCH-FREE body.
// All lanes uniformly load se/ve0/ve1/ve2; slot-type dispatch via loop-
// invariant predicated selects instead of nested divergent branches.
// Lane math identical to rounds 1/4 (verified):
//   producer lane P computes w[path=P>>3][4*(P&7)..+3]
//   consumer lane L owns quad qA = slot(L>>4), chans 4*(L&15);  qB = slot+2
// ---------------------------------------------------------------------------
__global__ void __launch_bounds__(256) edge_kernel(
    const float* __restrict__ ef,
    const float* __restrict__ radial,
    const int*   __restrict__ snd_,
    const int*   __restrict__ rcv_,
    const float* __restrict__ Wr1,   // (8,8)
    const float* __restrict__ Wr2,   // (8,128)
    int E)
{
    int warp = (blockIdx.x * blockDim.x + threadIdx.x) >> 5;
    int lane = threadIdx.x & 31;
    int base = warp * 8;
    if (base >= E) return;

    const float inv_sqrt8 = 0.35355339059327373f;
    const float inv_sqrt3 = 0.5773502691896258f;
    const float wk        = 0.08838834764831845f; // inv_sqrt8 * 1/sqrt(16)

    int grp  = lane >> 3;
    int srcA = (grp == 0) ? lane : ((grp == 1) ? lane + 16 : lane - 8);
    int srcB = (grp < 2)  ? lane + 8 : srcA;
    int cidx = (lane & 7) * 4;
    int jj   = lane & 7;
    int loff = (lane >> 4) * 64 + (lane & 15) * 4;

    // loop-invariant slot-type predicates
    bool g0 = (grp == 0), g1 = (grp == 1), g2 = (grp == 2);
    bool scalA = ((grp & 1) == 0);   // bA/bB base = se for grp 0,2

    // Per-warp invariant weights
    float wr1r[8];
    #pragma unroll
    for (int i = 0; i < 8; ++i) wr1r[i] = __ldg(Wr1 + i * 8 + jj);
    float4 wr2r[8];
    #pragma unroll
    for (int q = 0; q < 8; ++q) wr2r[q] = __ldg((const float4*)(Wr2 + q * 128 + lane * 4));

    // Batch-load 8 edges' indices (lanes 0-7; clamped for tail safety)
    int eic = base + jj; if (eic > E - 1) eic = E - 1;
    int snd8 = __ldg(snd_ + eic);
    int rcv8 = __ldg(rcv_ + eic);

    // Batch-load 8 edges' radial (64 floats, coalesced): lane holds float2
    // covering floats [base*8 + 2*lane, +1]. Edge j's r_i: lane 4*j+(i>>1),
    // component i&1. Clamp for tail.
    size_t rbase = (size_t)base * 4 + lane;
    size_t rmax  = (size_t)E * 4 - 1;
    if (rbase > rmax) rbase = rmax;
    float2 rv = __ldg((const float2*)radial + rbase);
    float rvx = rv.x, rvy = rv.y;

    // Precompute hidden activations for all 8 edges:
    // lane holds h[edge = lane>>3][hidden = lane&7] in h0, and edge+4 in h1.
    float h0, h1;
    {
        int eb = (lane >> 3) * 4;  // source lane base for this lane's edge
        float t0 = 0.f, t1 = 0.f;
        #pragma unroll
        for (int i = 0; i < 8; ++i) {
            int sl = eb + (i >> 1);
            float r0 = (i & 1) ? __shfl_sync(0xffffffffu, rvy, sl)
                               : __shfl_sync(0xffffffffu, rvx, sl);
            float r1 = (i & 1) ? __shfl_sync(0xffffffffu, rvy, sl + 16)
                               : __shfl_sync(0xffffffffu, rvx, sl + 16);
            t0 = fmaf(r0, wr1r[i], t0);
            t1 = fmaf(r1, wr1r[i], t1);
        }
        h0 = silu_f(t0 * inv_sqrt8);
        h1 = silu_f(t1 * inv_sqrt8);
    }

    #pragma unroll
    for (int j = 0; j < 8; ++j) {
        bool vj = (base + j) < E;
        int snd = __shfl_sync(0xffffffffu, snd8, j);
        int rcv = __shfl_sync(0xffffffffu, rcv8, j);

        // producer w from register-resident Wr2 and batched h
        float w0 = 0.f, w1 = 0.f, w2 = 0.f, w3 = 0.f;
        #pragma unroll
        for (int q = 0; q < 8; ++q) {
            float hq = (j < 4) ? __shfl_sync(0xffffffffu, h0, (j & 3) * 8 + q)
                               : __shfl_sync(0xffffffffu, h1, (j & 3) * 8 + q);
            w0 = fmaf(hq, wr2r[q].x, w0);
            w1 = fmaf(hq, wr2r[q].y, w1);
            w2 = fmaf(hq, wr2r[q].z, w2);
            w3 = fmaf(hq, wr2r[q].w, w3);
        }
        w0 *= wk; w1 *= wk; w2 *= wk; w3 *= wk;  // folds 1/sqrt(R_HID) and 1/sqrt(deg)

        float wA0 = __shfl_sync(0xffffffffu, w0, srcA);
        float wA1 = __shfl_sync(0xffffffffu, w1, srcA);
        float wA2 = __shfl_sync(0xffffffffu, w2, srcA);
        float wA3 = __shfl_sync(0xffffffffu, w3, srcA);
        float wB0 = __shfl_sync(0xffffffffu, w0, srcB);
        float wB1 = __shfl_sync(0xffffffffu, w1, srcB);
        float wB2 = __shfl_sync(0xffffffffu, w2, srcB);
        float wB3 = __shfl_sync(0xffffffffu, w3, srcB);

        int ee = vj ? (base + j) : (E - 1);
        float4 sh = __ldg((const float4*)ef + ee);           // broadcast

        // Uniform gathers (no divergence): all lanes load se + full ve
        const float* vb = g_vup + (size_t)snd * 96 + cidx;
        float4 se  = __ldg((const float4*)(g_sup + (size_t)snd * 32 + cidx));
        float4 ve0 = __ldg((const float4*)(vb));
        float4 ve1 = __ldg((const float4*)(vb + 32));
        float4 ve2 = __ldg((const float4*)(vb + 64));

        // dot(ve, sh1) per channel (used by grp1 qA)
        float d0 = fmaf(ve2.x, sh.w, fmaf(ve1.x, sh.z, ve0.x * sh.y));
        float d1 = fmaf(ve2.y, sh.w, fmaf(ve1.y, sh.z, ve0.y * sh.y));
        float d2 = fmaf(ve2.z, sh.w, fmaf(ve1.z, sh.z, ve0.z * sh.y));
        float d3 = fmaf(ve2.w, sh.w, fmaf(ve1.w, sh.z, ve0.w * sh.y));

        // slot-type dispatch via selects (predicates loop-invariant)
        float sA = g1 ? inv_sqrt3 : (g2 ? sh.y : sh.x);
        float sB = g0 ? sh.z : (g2 ? sh.w : sh.x);

        float bA0 = scalA ? se.x : (g1 ? d0 : ve0.x);
        float bA1 = scalA ? se.y : (g1 ? d1 : ve0.y);
        float bA2 = scalA ? se.z : (g1 ? d2 : ve0.z);
        float bA3 = scalA ? se.w : (g1 ? d3 : ve0.w);

        float bB0 = scalA ? se.x : (g1 ? ve1.x : ve2.x);
        float bB1 = scalA ? se.y : (g1 ? ve1.y : ve2.y);
        float bB2 = scalA ? se.z : (g1 ? ve1.z : ve2.z);
        float bB3 = scalA ? se.w : (g1 ? ve1.w : ve2.w);

        float* dst = g_agg + (size_t)rcv * 256 + loff;
        if (vj) {
            red_add_v4(dst,
                       (wA0 * sA) * bA0, (wA1 * sA) * bA1,
                       (wA2 * sA) * bA2, (wA3 * sA) * bA3);
            red_add_v4(dst + 128,
                       (wB0 * sB) * bB0, (wB1 * sB) * bB1,
                       (wB2 * sB) * bB2, (wB3 * sB) * bB3);
        }
    }
}

// ---------------------------------------------------------------------------
// Kernel C: per-node down-projection + skip average + gated output (UNCHANGED).
// ---------------------------------------------------------------------------
__global__ void node_down_kernel(const float* __restrict__ Wds,  // (64,64)
                                 const float* __restrict__ Wdv,  // (64,32)
                                 float* __restrict__ out,
                                 int N)
{
    int warp = (blockIdx.x * blockDim.x + threadIdx.x) >> 5;
    int lane = threadIdx.x & 31;
    if (warp >= N) return;
    int n = warp;

    const float* ag = g_agg + (size_t)n * 256;
    float a0l  = ag[lane],        a0h  = ag[32 + lane];
    float a1l0 = ag[64 + lane],   a1h0 = ag[96 + lane];
    float a1l1 = ag[128 + lane],  a1h1 = ag[160 + lane];
    float a1l2 = ag[192 + lane],  a1h2 = ag[224 + lane];

    float sc0 = 0.f, sc1 = 0.f, vc0 = 0.f, vc1 = 0.f, vc2 = 0.f;

    #pragma unroll
    for (int c = 0; c < 32; ++c) {
        float b0 = __shfl_sync(0xffffffffu, a0l, c);
        float b1 = __shfl_sync(0xffffffffu, a0h, c);
        sc0 = fmaf(b0, __ldg(Wds + c * 64 + lane), sc0);
        sc0 = fmaf(b1, __ldg(Wds + (32 + c) * 64 + lane), sc0);
        sc1 = fmaf(b0, __ldg(Wds + c * 64 + 32 + lane), sc1);
        sc1 = fmaf(b1, __ldg(Wds + (32 + c) * 64 + 32 + lane), sc1);
        float wv0 = __ldg(Wdv + c * 32 + lane);
        float wv1 = __ldg(Wdv + (32 + c) * 32 + lane);
        vc0 = fmaf(__shfl_sync(0xffffffffu, a1l0, c), wv0, vc0);
        vc0 = fmaf(__shfl_sync(0xffffffffu, a1h0, c), wv1, vc0);
        vc1 = fmaf(__shfl_sync(0xffffffffu, a1l1, c), wv0, vc1);
        vc1 = fmaf(__shfl_sync(0xffffffffu, a1h1, c), wv1, vc1);
        vc2 = fmaf(__shfl_sync(0xffffffffu, a1l2, c), wv0, vc2);
        vc2 = fmaf(__shfl_sync(0xffffffffu, a1h2, c), wv1, vc2);
    }

    const float i2c = 0.125f; // 1/sqrt(64)
    float scl = 0.5f * (sc0 * i2c + g_skip_s[n * 64 + lane]);
    float sch = 0.5f * (sc1 * i2c + g_skip_s[n * 64 + 32 + lane]);
    float feat = silu_f(scl);
    float gate = silu_f(sch);

    float vg0 = 0.5f * (vc0 * i2c + g_skip_v[n * 96 +      lane]) * gate;
    float vg1 = 0.5f * (vc1 * i2c + g_skip_v[n * 96 + 32 + lane]) * gate;
    float vg2 = 0.5f * (vc2 * i2c + g_skip_v[n * 96 + 64 + lane]) * gate;

    float* o = out + (size_t)n * 128;
    o[lane] = feat;
    o[32 + 3 * lane + 0] = vg0;
    o[32 + 3 * lane + 1] = vg1;
    o[32 + 3 * lane + 2] = vg2;
}

// ---------------------------------------------------------------------------
extern "C" void kernel_launch(void* const* d_in, const int* in_sizes, int n_in,
                              void* d_out, int out_size)
{
    const float* nf      = (const float*)d_in[0];
    const float* ef      = (const float*)d_in[1];
    const float* radial  = (const float*)d_in[2];
    const int*   snd     = (const int*)  d_in[3];
    const int*   rcv     = (const int*)  d_in[4];
    const int*   species = (const int*)  d_in[5];
    const float* Wus     = (const float*)d_in[6];
    const float* Wuv     = (const float*)d_in[7];
    const float* Wr1     = (const float*)d_in[8];
    const float* Wr2     = (const float*)d_in[9];
    const float* Wds     = (const float*)d_in[10];
    const float* Wdv     = (const float*)d_in[11];
    const float* Wss     = (const float*)d_in[12];
    const float* Wsv     = (const float*)d_in[13];
    float* out = (float*)d_out;

    int N = in_sizes[0] / 128;
    int E = in_sizes[3];

    int ewarps  = (E + 7) / 8;
    int eblocks = (ewarps + 7) / 8;

    node_up_kernel  <<<(N + 7) / 8, 256>>>(nf, species, Wus, Wuv, Wss, Wsv, N);
    edge_kernel     <<<eblocks, 256>>>(ef, radial, snd, rcv, Wr1, Wr2, E);
    node_down_kernel<<<(N + 7) / 8, 256>>>(Wds, Wdv, out, N);
}